// round 1
// baseline (speedup 1.0000x reference)
#include <cuda_runtime.h>

typedef unsigned long long u64;

__device__ __forceinline__ u64 fma2(u64 a, u64 b, u64 c) {
    u64 d;
    asm("fma.rn.f32x2 %0, %1, %2, %3;" : "=l"(d) : "l"(a), "l"(b), "l"(c));
    return d;
}
__device__ __forceinline__ u64 dup2(float v) {
    u64 d;
    asm("mov.b64 %0, {%1, %1};" : "=l"(d) : "f"(v));
    return d;
}
__device__ __forceinline__ void unpk(u64 a, float& x, float& y) {
    asm("mov.b64 {%0, %1}, %2;" : "=f"(x), "=f"(y) : "l"(a));
}
__device__ __forceinline__ float lrelu(float x) { return fmaxf(x, 0.01f * x); }

// SMEM layout (float offsets). All u64-loaded regions start at even offsets.
#define OFF_ZP   0        // zpad:  5*36*36 = 6480   (halo stays 0)
#define OFF_H1   6480     // h1pad: 6*36*36 = 7776   (doubles as xpad during setup)
#define OFF_C1X  14256    // c1x:   1024*6  = 6144   (pixel-major, channel-interleaved)
#define OFF_W1Z  20400    // w1z:   125*6   = 750    (tap-major, out-ch interleaved)
#define OFF_W2T  21150    // w2t:   150*6   = 900    (out-ch padded 5->6)
#define OFF_B2   22050    // b2 padded to 6
#define OFF_W1X  22056    // w1x:   75*6    = 450
#define SMEM_FLOATS 22506
#define SMEM_BYTES (SMEM_FLOATS * 4)

__global__ void __launch_bounds__(256, 2)
deq_kernel(const float* __restrict__ image,
           const float* __restrict__ w1, const float* __restrict__ b1,
           const float* __restrict__ w2, const float* __restrict__ b2,
           const float* __restrict__ wh, const float* __restrict__ bh,
           float* __restrict__ out)
{
    extern __shared__ float sm[];
    float* zp  = sm + OFF_ZP;
    float* h1  = sm + OFF_H1;
    float* c1x = sm + OFF_C1X;
    float* w1z = sm + OFF_W1Z;
    float* w2t = sm + OFF_W2T;
    float* b2s = sm + OFF_B2;
    float* w1x = sm + OFF_W1X;

    const int n = blockIdx.x;
    const int t = threadIdx.x;
    const float* img = image + n * 3072;

    // ---- setup: zero pads, stage weights (re-layout for packed loads) ----
    for (int i = t; i < 6480; i += 256) zp[i] = 0.f;
    float* xp = h1;  // reuse h1 region as padded image during precompute
    for (int i = t; i < 3888; i += 256) xp[i] = 0.f;
    for (int i = t; i < 750; i += 256) {          // w1 z-part: [tap(c,ky,kx)][j]
        int tap = i / 6, j = i - tap * 6;
        int c = tap / 25, k = tap - c * 25;
        w1z[i] = w1[(j * 8 + c) * 25 + k];
    }
    for (int i = t; i < 450; i += 256) {          // w1 image-part
        int tap = i / 6, j = i - tap * 6;
        int c = tap / 25, k = tap - c * 25;
        w1x[i] = w1[(j * 8 + 5 + c) * 25 + k];
    }
    for (int i = t; i < 900; i += 256) {          // w2: pad out-channels to 6
        int tap = i / 6, j = i - tap * 6;
        w2t[i] = (j < 5) ? w2[j * 150 + tap] : 0.f;
    }
    if (t < 6) b2s[t] = (t < 5) ? b2[t] : 0.f;
    __syncthreads();
    for (int i = t; i < 3072; i += 256) {         // image interior into xpad
        int c = i >> 10, rr = (i >> 5) & 31, cc = i & 31;
        xp[c * 1296 + (rr + 2) * 36 + (cc + 2)] = img[i];
    }
    __syncthreads();

    const int r  = t >> 3;          // output row 0..31
    const int c0 = (t & 7) << 2;    // output col base 0,4,...,28

    // ---- precompute c1x = conv1_x(image) + b1 (iteration-invariant) ----
    {
        float a[4][6];
        #pragma unroll
        for (int p = 0; p < 4; ++p)
            #pragma unroll
            for (int j = 0; j < 6; ++j) a[p][j] = b1[j];
        #pragma unroll 1
        for (int c = 0; c < 3; ++c) {
            const float* xb = xp + c * 1296 + r * 36 + c0;
            #pragma unroll
            for (int ky = 0; ky < 5; ++ky) {
                float4 va = *(const float4*)(xb + ky * 36);
                float4 vb = *(const float4*)(xb + ky * 36 + 4);
                float rv[8] = {va.x, va.y, va.z, va.w, vb.x, vb.y, vb.z, vb.w};
                const float* wr = w1x + (c * 25 + ky * 5) * 6;
                #pragma unroll
                for (int kx = 0; kx < 5; ++kx)
                    #pragma unroll
                    for (int j = 0; j < 6; ++j) {
                        float wv = wr[kx * 6 + j];
                        #pragma unroll
                        for (int p = 0; p < 4; ++p)
                            a[p][j] = fmaf(rv[p + kx], wv, a[p][j]);
                    }
            }
        }
        #pragma unroll
        for (int p = 0; p < 4; ++p)
            #pragma unroll
            for (int j = 0; j < 6; ++j)
                c1x[(r * 32 + c0 + p) * 6 + j] = a[p][j];
    }
    __syncthreads();                 // all xpad reads done
    for (int i = t; i < 7776; i += 256) h1[i] = 0.f;   // zero h1 (halo must be 0)

    float zreg[5][4];
    #pragma unroll
    for (int j = 0; j < 5; ++j)
        #pragma unroll
        for (int p = 0; p < 4; ++p) zreg[j][p] = 0.f;

    const u64 b01 = *(const u64*)(b2s + 0);
    const u64 b23 = *(const u64*)(b2s + 2);
    const u64 b45 = *(const u64*)(b2s + 4);
    const int pixbase = (r * 32 + c0) * 6;
    __syncthreads();

    // ---- 150 damped fixed-point iterations, all in SMEM ----
    #pragma unroll 1
    for (int it = 0; it < 150; ++it) {
        // conv1 over z channels (packed out-channel pairs (0,1),(2,3),(4,5))
        u64 a0[4], a1[4], a2[4];
        #pragma unroll
        for (int p = 0; p < 4; ++p) {
            a0[p] = *(const u64*)(c1x + pixbase + p * 6 + 0);
            a1[p] = *(const u64*)(c1x + pixbase + p * 6 + 2);
            a2[p] = *(const u64*)(c1x + pixbase + p * 6 + 4);
        }
        #pragma unroll 1
        for (int c = 0; c < 5; ++c) {
            const float* zb = zp + c * 1296 + r * 36 + c0;
            #pragma unroll
            for (int ky = 0; ky < 5; ++ky) {
                float4 va = *(const float4*)(zb + ky * 36);
                float4 vb = *(const float4*)(zb + ky * 36 + 4);
                u64 zz[8];
                zz[0] = dup2(va.x); zz[1] = dup2(va.y); zz[2] = dup2(va.z); zz[3] = dup2(va.w);
                zz[4] = dup2(vb.x); zz[5] = dup2(vb.y); zz[6] = dup2(vb.z); zz[7] = dup2(vb.w);
                const float* wr = w1z + (c * 25 + ky * 5) * 6;
                #pragma unroll
                for (int kx = 0; kx < 5; ++kx) {
                    u64 w01 = *(const u64*)(wr + kx * 6 + 0);
                    u64 w23 = *(const u64*)(wr + kx * 6 + 2);
                    u64 w45 = *(const u64*)(wr + kx * 6 + 4);
                    #pragma unroll
                    for (int p = 0; p < 4; ++p) {
                        a0[p] = fma2(zz[p + kx], w01, a0[p]);
                        a1[p] = fma2(zz[p + kx], w23, a1[p]);
                        a2[p] = fma2(zz[p + kx], w45, a2[p]);
                    }
                }
            }
        }
        // leaky + write h1 (planar, float2 stores)
        {
            float hv[6][4];
            #pragma unroll
            for (int p = 0; p < 4; ++p) {
                float x0, x1, x2, x3, x4, x5;
                unpk(a0[p], x0, x1); unpk(a1[p], x2, x3); unpk(a2[p], x4, x5);
                hv[0][p] = lrelu(x0); hv[1][p] = lrelu(x1); hv[2][p] = lrelu(x2);
                hv[3][p] = lrelu(x3); hv[4][p] = lrelu(x4); hv[5][p] = lrelu(x5);
            }
            #pragma unroll
            for (int j = 0; j < 6; ++j) {
                float* hb = h1 + j * 1296 + (r + 2) * 36 + (c0 + 2);
                *(float2*)(hb)     = make_float2(hv[j][0], hv[j][1]);
                *(float2*)(hb + 2) = make_float2(hv[j][2], hv[j][3]);
            }
        }
        __syncthreads();

        // conv2 (6 in-ch, 5 out-ch padded to 6)
        u64 d0[4], d1[4], d2[4];
        #pragma unroll
        for (int p = 0; p < 4; ++p) { d0[p] = b01; d1[p] = b23; d2[p] = b45; }
        #pragma unroll 1
        for (int c = 0; c < 6; ++c) {
            const float* hb = h1 + c * 1296 + r * 36 + c0;
            #pragma unroll
            for (int ky = 0; ky < 5; ++ky) {
                float4 va = *(const float4*)(hb + ky * 36);
                float4 vb = *(const float4*)(hb + ky * 36 + 4);
                u64 zz[8];
                zz[0] = dup2(va.x); zz[1] = dup2(va.y); zz[2] = dup2(va.z); zz[3] = dup2(va.w);
                zz[4] = dup2(vb.x); zz[5] = dup2(vb.y); zz[6] = dup2(vb.z); zz[7] = dup2(vb.w);
                const float* wr = w2t + (c * 25 + ky * 5) * 6;
                #pragma unroll
                for (int kx = 0; kx < 5; ++kx) {
                    u64 w01 = *(const u64*)(wr + kx * 6 + 0);
                    u64 w23 = *(const u64*)(wr + kx * 6 + 2);
                    u64 w45 = *(const u64*)(wr + kx * 6 + 4);
                    #pragma unroll
                    for (int p = 0; p < 4; ++p) {
                        d0[p] = fma2(zz[p + kx], w01, d0[p]);
                        d1[p] = fma2(zz[p + kx], w23, d1[p]);
                        d2[p] = fma2(zz[p + kx], w45, d2[p]);
                    }
                }
            }
        }
        // z <- 0.5*(z + leaky(conv2))  (register copy of own z + SMEM write)
        {
            #pragma unroll
            for (int p = 0; p < 4; ++p) {
                float x0, x1, x2, x3, x4, x5;
                unpk(d0[p], x0, x1); unpk(d1[p], x2, x3); unpk(d2[p], x4, x5);
                zreg[0][p] = 0.5f * (zreg[0][p] + lrelu(x0));
                zreg[1][p] = 0.5f * (zreg[1][p] + lrelu(x1));
                zreg[2][p] = 0.5f * (zreg[2][p] + lrelu(x2));
                zreg[3][p] = 0.5f * (zreg[3][p] + lrelu(x3));
                zreg[4][p] = 0.5f * (zreg[4][p] + lrelu(x4));
            }
            #pragma unroll
            for (int j = 0; j < 5; ++j) {
                float* zb2 = zp + j * 1296 + (r + 2) * 36 + (c0 + 2);
                *(float2*)(zb2)     = make_float2(zreg[j][0], zreg[j][1]);
                *(float2*)(zb2 + 2) = make_float2(zreg[j][2], zreg[j][3]);
            }
        }
        __syncthreads();
    }

    // ---- class head: logits[o] = bh[o] + <z, wh[o]> ----
    float part[10];
    #pragma unroll
    for (int o = 0; o < 10; ++o) part[o] = 0.f;
    #pragma unroll 1
    for (int i = t; i < 5120; i += 256) {
        int c = i >> 10, rr = (i >> 5) & 31, cc = i & 31;
        float zv = zp[c * 1296 + (rr + 2) * 36 + (cc + 2)];
        #pragma unroll
        for (int o = 0; o < 10; ++o)
            part[o] = fmaf(zv, wh[o * 5120 + i], part[o]);
    }
    float* red = c1x;  // reuse as reduction scratch
    #pragma unroll
    for (int o = 0; o < 10; ++o) red[t * 10 + o] = part[o];
    __syncthreads();
    if (t < 10) {
        float s = bh[t];
        for (int k = 0; k < 256; ++k) s += red[k * 10 + t];
        out[n * 10 + t] = s;
    }
}

extern "C" void kernel_launch(void* const* d_in, const int* in_sizes, int n_in,
                              void* d_out, int out_size) {
    const float* image = (const float*)d_in[0];
    const float* w1    = (const float*)d_in[1];
    const float* b1    = (const float*)d_in[2];
    const float* w2    = (const float*)d_in[3];
    const float* b2    = (const float*)d_in[4];
    const float* wh    = (const float*)d_in[5];
    const float* bh    = (const float*)d_in[6];
    float* out = (float*)d_out;

    const int N = in_sizes[0] / 3072;  // 512 images
    cudaFuncSetAttribute(deq_kernel, cudaFuncAttributeMaxDynamicSharedMemorySize, SMEM_BYTES);
    deq_kernel<<<N, 256, SMEM_BYTES>>>(image, w1, b1, w2, b2, wh, bh, out);
}

// round 2
// speedup vs baseline: 1.3880x; 1.3880x over previous
#include <cuda_runtime.h>

typedef unsigned long long u64;

__device__ __forceinline__ u64 fma2(u64 a, u64 b, u64 c) {
    u64 d;
    asm("fma.rn.f32x2 %0, %1, %2, %3;" : "=l"(d) : "l"(a), "l"(b), "l"(c));
    return d;
}
__device__ __forceinline__ u64 dup2(float v) {
    u64 d;
    asm("mov.b64 %0, {%1, %1};" : "=l"(d) : "f"(v));
    return d;
}
__device__ __forceinline__ void unpk(u64 a, float& x, float& y) {
    asm("mov.b64 {%0, %1}, %2;" : "=f"(x), "=f"(y) : "l"(a));
}
__device__ __forceinline__ float lrelu(float x) { return fmaxf(x, 0.01f * x); }

// SMEM layout (float offsets). All u64/128b-loaded regions properly aligned.
#define OFF_ZP   0        // zpad:  5*36*36 = 6480   (halo stays 0)
#define OFF_H1   6480     // h1pad: 6*36*36 = 7776   (doubles as xpad during setup)
#define OFF_C1X  14256    // c1x:   1024*6  = 6144   (pixel-major, channel-interleaved)
#define OFF_W1Z  20400    // w1z:   125*8   = 1000   (tap-major stride 8, out-ch interleaved)
#define OFF_W2T  21400    // w2t:   150*8   = 1200   (out-ch padded 5->6, stride 8)
#define OFF_B2   22600    // b2 padded to 8
#define OFF_W1X  22608    // w1x:   75*6    = 450
#define SMEM_FLOATS 23058
#define SMEM_BYTES (SMEM_FLOATS * 4)

__global__ void __launch_bounds__(512, 2)
deq_kernel(const float* __restrict__ image,
           const float* __restrict__ w1, const float* __restrict__ b1,
           const float* __restrict__ w2, const float* __restrict__ b2,
           const float* __restrict__ wh, const float* __restrict__ bh,
           float* __restrict__ out)
{
    extern __shared__ float sm[];
    float* zp  = sm + OFF_ZP;
    float* h1  = sm + OFF_H1;
    float* c1x = sm + OFF_C1X;
    float* w1z = sm + OFF_W1Z;
    float* w2t = sm + OFF_W2T;
    float* b2s = sm + OFF_B2;
    float* w1x = sm + OFF_W1X;

    const int n = blockIdx.x;
    const int t = threadIdx.x;
    const float* img = image + n * 3072;

    // ---- setup: zero pads, stage weights (re-layout for packed loads) ----
    for (int i = t; i < 6480; i += 512) zp[i] = 0.f;
    float* xp = h1;  // reuse h1 region as padded image during precompute
    for (int i = t; i < 3888; i += 512) xp[i] = 0.f;
    for (int i = t; i < 1000; i += 512) {         // w1 z-part: [tap(c,ky,kx)]*8 + j
        int tap = i >> 3, j = i & 7;
        int c = tap / 25, k = tap - c * 25;
        w1z[i] = (j < 6) ? w1[(j * 8 + c) * 25 + k] : 0.f;
    }
    for (int i = t; i < 450; i += 512) {          // w1 image-part (stride 6, setup only)
        int tap = i / 6, j = i - tap * 6;
        int c = tap / 25, k = tap - c * 25;
        w1x[i] = w1[(j * 8 + 5 + c) * 25 + k];
    }
    for (int i = t; i < 1200; i += 512) {         // w2: pad out-channels to 6, stride 8
        int tap = i >> 3, j = i & 7;
        w2t[i] = (j < 5) ? w2[j * 150 + tap] : 0.f;
    }
    if (t < 8) b2s[t] = (t < 5) ? b2[t] : 0.f;
    __syncthreads();
    for (int i = t; i < 3072; i += 512) {         // image interior into xpad
        int c = i >> 10, rr = (i >> 5) & 31, cc = i & 31;
        xp[c * 1296 + (rr + 2) * 36 + (cc + 2)] = img[i];
    }
    __syncthreads();

    const int r  = t >> 4;          // output row 0..31
    const int c0 = (t & 15) << 1;   // output col base 0,2,...,30 (2 pixels/thread)

    // ---- precompute c1x = conv1_x(image) + b1 (iteration-invariant) ----
    {
        float a[2][6];
        #pragma unroll
        for (int p = 0; p < 2; ++p)
            #pragma unroll
            for (int j = 0; j < 6; ++j) a[p][j] = b1[j];
        #pragma unroll 1
        for (int c = 0; c < 3; ++c) {
            const float* xb = xp + c * 1296 + r * 36 + c0;
            #pragma unroll
            for (int ky = 0; ky < 5; ++ky) {
                float rv[6];
                #pragma unroll
                for (int q = 0; q < 6; ++q) rv[q] = xb[ky * 36 + q];
                const float* wr = w1x + (c * 25 + ky * 5) * 6;
                #pragma unroll
                for (int kx = 0; kx < 5; ++kx)
                    #pragma unroll
                    for (int j = 0; j < 6; ++j) {
                        float wv = wr[kx * 6 + j];
                        #pragma unroll
                        for (int p = 0; p < 2; ++p)
                            a[p][j] = fmaf(rv[p + kx], wv, a[p][j]);
                    }
            }
        }
        #pragma unroll
        for (int p = 0; p < 2; ++p)
            #pragma unroll
            for (int j = 0; j < 6; ++j)
                c1x[(r * 32 + c0 + p) * 6 + j] = a[p][j];
    }
    __syncthreads();                 // all xpad reads done
    for (int i = t; i < 7776; i += 512) h1[i] = 0.f;   // zero h1 (halo must be 0)

    float zreg[5][2];
    #pragma unroll
    for (int j = 0; j < 5; ++j)
        #pragma unroll
        for (int p = 0; p < 2; ++p) zreg[j][p] = 0.f;

    const u64 b01 = *(const u64*)(b2s + 0);
    const u64 b23 = *(const u64*)(b2s + 2);
    const u64 b45 = *(const u64*)(b2s + 4);
    const int pixbase = (r * 32 + c0) * 6;
    __syncthreads();

    // ---- 150 damped fixed-point iterations, all in SMEM ----
    #pragma unroll 1
    for (int it = 0; it < 150; ++it) {
        // conv1 over z channels (packed out-channel pairs (0,1),(2,3),(4,5))
        u64 a0[2], a1[2], a2[2];
        #pragma unroll
        for (int p = 0; p < 2; ++p) {
            a0[p] = *(const u64*)(c1x + pixbase + p * 6 + 0);
            a1[p] = *(const u64*)(c1x + pixbase + p * 6 + 2);
            a2[p] = *(const u64*)(c1x + pixbase + p * 6 + 4);
        }
        #pragma unroll 1
        for (int c = 0; c < 5; ++c) {
            const float* zb = zp + c * 1296 + r * 36 + c0;
            #pragma unroll
            for (int ky = 0; ky < 5; ++ky) {
                float2 v0 = *(const float2*)(zb + ky * 36);
                float2 v1 = *(const float2*)(zb + ky * 36 + 2);
                float2 v2 = *(const float2*)(zb + ky * 36 + 4);
                u64 zz[6];
                zz[0] = dup2(v0.x); zz[1] = dup2(v0.y);
                zz[2] = dup2(v1.x); zz[3] = dup2(v1.y);
                zz[4] = dup2(v2.x); zz[5] = dup2(v2.y);
                const float* wr = w1z + (c * 25 + ky * 5) * 8;
                #pragma unroll
                for (int kx = 0; kx < 5; ++kx) {
                    ulonglong2 wq = *(const ulonglong2*)(wr + kx * 8);
                    u64 w45 = *(const u64*)(wr + kx * 8 + 4);
                    #pragma unroll
                    for (int p = 0; p < 2; ++p) {
                        a0[p] = fma2(zz[p + kx], wq.x, a0[p]);
                        a1[p] = fma2(zz[p + kx], wq.y, a1[p]);
                        a2[p] = fma2(zz[p + kx], w45, a2[p]);
                    }
                }
            }
        }
        // leaky + write h1 (planar, float2 stores)
        {
            float hv[6][2];
            #pragma unroll
            for (int p = 0; p < 2; ++p) {
                float x0, x1, x2, x3, x4, x5;
                unpk(a0[p], x0, x1); unpk(a1[p], x2, x3); unpk(a2[p], x4, x5);
                hv[0][p] = lrelu(x0); hv[1][p] = lrelu(x1); hv[2][p] = lrelu(x2);
                hv[3][p] = lrelu(x3); hv[4][p] = lrelu(x4); hv[5][p] = lrelu(x5);
            }
            #pragma unroll
            for (int j = 0; j < 6; ++j) {
                float* hb = h1 + j * 1296 + (r + 2) * 36 + (c0 + 2);
                *(float2*)(hb) = make_float2(hv[j][0], hv[j][1]);
            }
        }
        __syncthreads();

        // conv2 (6 in-ch, 5 out-ch padded to 6)
        u64 d0[2], d1[2], d2[2];
        #pragma unroll
        for (int p = 0; p < 2; ++p) { d0[p] = b01; d1[p] = b23; d2[p] = b45; }
        #pragma unroll 1
        for (int c = 0; c < 6; ++c) {
            const float* hb = h1 + c * 1296 + r * 36 + c0;
            #pragma unroll
            for (int ky = 0; ky < 5; ++ky) {
                float2 v0 = *(const float2*)(hb + ky * 36);
                float2 v1 = *(const float2*)(hb + ky * 36 + 2);
                float2 v2 = *(const float2*)(hb + ky * 36 + 4);
                u64 zz[6];
                zz[0] = dup2(v0.x); zz[1] = dup2(v0.y);
                zz[2] = dup2(v1.x); zz[3] = dup2(v1.y);
                zz[4] = dup2(v2.x); zz[5] = dup2(v2.y);
                const float* wr = w2t + (c * 25 + ky * 5) * 8;
                #pragma unroll
                for (int kx = 0; kx < 5; ++kx) {
                    ulonglong2 wq = *(const ulonglong2*)(wr + kx * 8);
                    u64 w45 = *(const u64*)(wr + kx * 8 + 4);
                    #pragma unroll
                    for (int p = 0; p < 2; ++p) {
                        d0[p] = fma2(zz[p + kx], wq.x, d0[p]);
                        d1[p] = fma2(zz[p + kx], wq.y, d1[p]);
                        d2[p] = fma2(zz[p + kx], w45, d2[p]);
                    }
                }
            }
        }
        // z <- 0.5*(z + leaky(conv2))  (register copy of own z + SMEM write)
        {
            #pragma unroll
            for (int p = 0; p < 2; ++p) {
                float x0, x1, x2, x3, x4, x5;
                unpk(d0[p], x0, x1); unpk(d1[p], x2, x3); unpk(d2[p], x4, x5);
                zreg[0][p] = 0.5f * (zreg[0][p] + lrelu(x0));
                zreg[1][p] = 0.5f * (zreg[1][p] + lrelu(x1));
                zreg[2][p] = 0.5f * (zreg[2][p] + lrelu(x2));
                zreg[3][p] = 0.5f * (zreg[3][p] + lrelu(x3));
                zreg[4][p] = 0.5f * (zreg[4][p] + lrelu(x4));
            }
            #pragma unroll
            for (int j = 0; j < 5; ++j) {
                float* zb2 = zp + j * 1296 + (r + 2) * 36 + (c0 + 2);
                *(float2*)(zb2) = make_float2(zreg[j][0], zreg[j][1]);
            }
        }
        __syncthreads();
    }

    // ---- class head: logits[o] = bh[o] + <z, wh[o]> ----
    float part[10];
    #pragma unroll
    for (int o = 0; o < 10; ++o) part[o] = 0.f;
    #pragma unroll 1
    for (int i = t; i < 5120; i += 512) {
        int c = i >> 10, rr = (i >> 5) & 31, cc = i & 31;
        float zv = zp[c * 1296 + (rr + 2) * 36 + (cc + 2)];
        #pragma unroll
        for (int o = 0; o < 10; ++o)
            part[o] = fmaf(zv, wh[o * 5120 + i], part[o]);
    }
    float* red = c1x;  // reuse as reduction scratch (512*10 = 5120 <= 6144)
    #pragma unroll
    for (int o = 0; o < 10; ++o) red[t * 10 + o] = part[o];
    __syncthreads();
    if (t < 10) {
        float s = bh[t];
        for (int k = 0; k < 512; ++k) s += red[k * 10 + t];
        out[n * 10 + t] = s;
    }
}

extern "C" void kernel_launch(void* const* d_in, const int* in_sizes, int n_in,
                              void* d_out, int out_size) {
    const float* image = (const float*)d_in[0];
    const float* w1    = (const float*)d_in[1];
    const float* b1    = (const float*)d_in[2];
    const float* w2    = (const float*)d_in[3];
    const float* b2    = (const float*)d_in[4];
    const float* wh    = (const float*)d_in[5];
    const float* bh    = (const float*)d_in[6];
    float* out = (float*)d_out;

    const int N = in_sizes[0] / 3072;  // 512 images
    cudaFuncSetAttribute(deq_kernel, cudaFuncAttributeMaxDynamicSharedMemorySize, SMEM_BYTES);
    deq_kernel<<<N, 512, SMEM_BYTES>>>(image, w1, b1, w2, b2, wh, bh, out);
}

// round 7
// speedup vs baseline: 1.4034x; 1.0111x over previous
#include <cuda_runtime.h>

typedef unsigned long long u64;

__device__ __forceinline__ u64 fma2(u64 a, u64 b, u64 c) {
    u64 d;
    asm("fma.rn.f32x2 %0, %1, %2, %3;" : "=l"(d) : "l"(a), "l"(b), "l"(c));
    return d;
}
__device__ __forceinline__ u64 dup2(float v) {
    u64 d;
    asm("mov.b64 %0, {%1, %1};" : "=l"(d) : "f"(v));
    return d;
}
__device__ __forceinline__ void unpk(u64 a, float& x, float& y) {
    asm("mov.b64 {%0, %1}, %2;" : "=f"(x), "=f"(y) : "l"(a));
}
__device__ __forceinline__ float lrelu(float x) { return fmaxf(x, 0.01f * x); }

// SMEM layout (float offsets)
#define OFF_ZP   0        // zpad: 6*36*36 = 7776 (plane 5 = scrap for conv2 pad ch)
#define OFF_H1   7776     // h1pad: 6*36*36 = 7776 (aliases xpad during setup; head scratch)
#define OFF_C1X  15552    // c1x: 3 pairs * 1024 pix * 2 = 6144 (pair-major, u64 per pixel)
#define OFF_W1P  21696    // w1 z-part packed: 3 pairs * 25 (c,ky) * 12 = 900
#define OFF_W2P  22596    // w2 packed: 3 pairs * 30 (c,ky) * 12 = 1080
#define OFF_B2   23676    // b2 padded to 8
#define OFF_W1X  23684    // w1 image-part: 75 taps * 6 = 450 (setup only)
#define SMEM_FLOATS 24134
#define SMEM_BYTES (SMEM_FLOATS * 4)

__global__ void __launch_bounds__(768, 2)
deq_kernel(const float* __restrict__ image,
           const float* __restrict__ w1, const float* __restrict__ b1,
           const float* __restrict__ w2, const float* __restrict__ b2,
           const float* __restrict__ wh, const float* __restrict__ bh,
           float* __restrict__ out)
{
    extern __shared__ float sm[];
    float* zp  = sm + OFF_ZP;
    float* h1  = sm + OFF_H1;
    float* c1x = sm + OFF_C1X;
    float* w1p = sm + OFF_W1P;
    float* w2p = sm + OFF_W2P;
    float* b2s = sm + OFF_B2;
    float* w1x = sm + OFF_W1X;

    const int n = blockIdx.x;
    const int t = threadIdx.x;
    const float* img = image + n * 3072;

    // ---- setup ----
    for (int i = t; i < 7776; i += 768) zp[i] = 0.f;
    float* xp = h1;  // alias: padded image during setup
    for (int i = t; i < 3888; i += 768) xp[i] = 0.f;
    // w1 z-part, pair-packed: [pair][c*5+ky][12] = {w2j(kx0),w2j+1(kx0),...,w2j(kx4),w2j+1(kx4),0,0}
    for (int i = t; i < 900; i += 768) {
        int jj = i / 300, rem = i - jj * 300;
        int cky = rem / 12, q = rem - cky * 12;
        int kx = q >> 1, ch = jj * 2 + (q & 1);
        int c = cky / 5, ky = cky - c * 5;
        w1p[i] = (kx < 5) ? w1[(ch * 8 + c) * 25 + ky * 5 + kx] : 0.f;
    }
    // w2, pair-packed (out-ch padded 5->6)
    for (int i = t; i < 1080; i += 768) {
        int jj = i / 360, rem = i - jj * 360;
        int cky = rem / 12, q = rem - cky * 12;
        int kx = q >> 1, ch = jj * 2 + (q & 1);
        int c = cky / 5, ky = cky - c * 5;
        w2p[i] = (kx < 5 && ch < 5) ? w2[ch * 150 + c * 25 + ky * 5 + kx] : 0.f;
    }
    // w1 image-part: tap-major stride 6 (channel pairs at even offsets)
    for (int i = t; i < 450; i += 768) {
        int tap = i / 6, jc = i - tap * 6;
        int c = tap / 25, k = tap - c * 25;
        w1x[i] = w1[(jc * 8 + 5 + c) * 25 + k];
    }
    if (t < 8) b2s[t] = (t < 5) ? b2[t] : 0.f;
    __syncthreads();
    for (int i = t; i < 3072; i += 768) {
        int c = i >> 10, rr = (i >> 5) & 31, cc = i & 31;
        xp[c * 1296 + (rr + 2) * 36 + (cc + 2)] = img[i];
    }
    __syncthreads();

    const int j  = t >> 8;            // out-channel pair 0..2
    const int g  = t & 255;           // pixel group
    const int r  = g >> 3;            // row 0..31
    const int c0 = (g & 7) << 2;      // col base 0,4,...,28 (4 pixels/thread)

    // ---- precompute c1x = conv1_x(image) + b1 for this pair ----
    {
        float a[4][2];
        #pragma unroll
        for (int p = 0; p < 4; ++p) { a[p][0] = b1[2 * j]; a[p][1] = b1[2 * j + 1]; }
        #pragma unroll 1
        for (int c = 0; c < 3; ++c) {
            const float* xb = xp + c * 1296 + r * 36 + c0;
            #pragma unroll
            for (int ky = 0; ky < 5; ++ky) {
                float4 va = *(const float4*)(xb + ky * 36);
                float4 vb = *(const float4*)(xb + ky * 36 + 4);
                float rv[8] = {va.x, va.y, va.z, va.w, vb.x, vb.y, vb.z, vb.w};
                const float* wr = w1x + (c * 25 + ky * 5) * 6 + 2 * j;
                #pragma unroll
                for (int kx = 0; kx < 5; ++kx) {
                    float2 wv = *(const float2*)(wr + kx * 6);
                    #pragma unroll
                    for (int p = 0; p < 4; ++p) {
                        a[p][0] = fmaf(rv[p + kx], wv.x, a[p][0]);
                        a[p][1] = fmaf(rv[p + kx], wv.y, a[p][1]);
                    }
                }
            }
        }
        float* cb = c1x + j * 2048 + (r * 32 + c0) * 2;
        *(float4*)(cb)     = make_float4(a[0][0], a[0][1], a[1][0], a[1][1]);
        *(float4*)(cb + 4) = make_float4(a[2][0], a[2][1], a[3][0], a[3][1]);
    }
    __syncthreads();                  // all xpad reads done
    for (int i = t; i < 7776; i += 768) h1[i] = 0.f;   // zero h1 (halo must be 0)

    const u64 bj = *(const u64*)(b2s + 2 * j);
    const float* cb = c1x + j * 2048 + (r * 32 + c0) * 2;
    __syncthreads();

    // ---- 150 damped fixed-point iterations ----
    #pragma unroll 1
    for (int it = 0; it < 150; ++it) {
        // conv1 over z (this thread: 4 pixels, out channels 2j,2j+1)
        u64 acc[4];
        {
            ulonglong2 A = *(const ulonglong2*)(cb);
            ulonglong2 B = *(const ulonglong2*)(cb + 4);
            acc[0] = A.x; acc[1] = A.y; acc[2] = B.x; acc[3] = B.y;
        }
        #pragma unroll 1
        for (int c = 0; c < 5; ++c) {
            const float* zb = zp + c * 1296 + r * 36 + c0;
            const float* wr = w1p + (j * 25 + c * 5) * 12;
            #pragma unroll
            for (int ky = 0; ky < 5; ++ky) {
                float4 va = *(const float4*)(zb + ky * 36);
                float4 vb = *(const float4*)(zb + ky * 36 + 4);
                u64 zz[8];
                zz[0] = dup2(va.x); zz[1] = dup2(va.y); zz[2] = dup2(va.z); zz[3] = dup2(va.w);
                zz[4] = dup2(vb.x); zz[5] = dup2(vb.y); zz[6] = dup2(vb.z); zz[7] = dup2(vb.w);
                ulonglong2 wA = *(const ulonglong2*)(wr + ky * 12);
                ulonglong2 wB = *(const ulonglong2*)(wr + ky * 12 + 4);
                u64 wC = *(const u64*)(wr + ky * 12 + 8);
                #pragma unroll
                for (int p = 0; p < 4; ++p) {
                    acc[p] = fma2(zz[p + 0], wA.x, acc[p]);
                    acc[p] = fma2(zz[p + 1], wA.y, acc[p]);
                    acc[p] = fma2(zz[p + 2], wB.x, acc[p]);
                    acc[p] = fma2(zz[p + 3], wB.y, acc[p]);
                    acc[p] = fma2(zz[p + 4], wC,   acc[p]);
                }
            }
        }
        // leaky + write h1 planes 2j, 2j+1
        {
            float h0[4], h1v[4];
            #pragma unroll
            for (int p = 0; p < 4; ++p) {
                float x, y; unpk(acc[p], x, y);
                h0[p] = lrelu(x); h1v[p] = lrelu(y);
            }
            float* hb0 = h1 + (2 * j) * 1296 + (r + 2) * 36 + (c0 + 2);
            float* hb1 = hb0 + 1296;
            *(float2*)(hb0)     = make_float2(h0[0], h0[1]);
            *(float2*)(hb0 + 2) = make_float2(h0[2], h0[3]);
            *(float2*)(hb1)     = make_float2(h1v[0], h1v[1]);
            *(float2*)(hb1 + 2) = make_float2(h1v[2], h1v[3]);
        }
        __syncthreads();

        // conv2 (reads all 6 h planes; out channels 2j,2j+1; pair 2's hi ch is pad)
        u64 d[4];
        #pragma unroll
        for (int p = 0; p < 4; ++p) d[p] = bj;
        #pragma unroll 1
        for (int c = 0; c < 6; ++c) {
            const float* hb = h1 + c * 1296 + r * 36 + c0;
            const float* wr = w2p + (j * 30 + c * 5) * 12;
            #pragma unroll
            for (int ky = 0; ky < 5; ++ky) {
                float4 va = *(const float4*)(hb + ky * 36);
                float4 vb = *(const float4*)(hb + ky * 36 + 4);
                u64 zz[8];
                zz[0] = dup2(va.x); zz[1] = dup2(va.y); zz[2] = dup2(va.z); zz[3] = dup2(va.w);
                zz[4] = dup2(vb.x); zz[5] = dup2(vb.y); zz[6] = dup2(vb.z); zz[7] = dup2(vb.w);
                ulonglong2 wA = *(const ulonglong2*)(wr + ky * 12);
                ulonglong2 wB = *(const ulonglong2*)(wr + ky * 12 + 4);
                u64 wC = *(const u64*)(wr + ky * 12 + 8);
                #pragma unroll
                for (int p = 0; p < 4; ++p) {
                    d[p] = fma2(zz[p + 0], wA.x, d[p]);
                    d[p] = fma2(zz[p + 1], wA.y, d[p]);
                    d[p] = fma2(zz[p + 2], wB.x, d[p]);
                    d[p] = fma2(zz[p + 3], wB.y, d[p]);
                    d[p] = fma2(zz[p + 4], wC,   d[p]);
                }
            }
        }
        // z <- 0.5*(z_old + leaky(conv2)); z_old re-read from own pixels (race-free)
        {
            float* zb0 = zp + (2 * j) * 1296 + (r + 2) * 36 + (c0 + 2);
            float* zb1 = zb0 + 1296;
            float2 oa = *(float2*)(zb0), ob = *(float2*)(zb0 + 2);
            float2 oc = *(float2*)(zb1), od = *(float2*)(zb1 + 2);
            float old0[4] = {oa.x, oa.y, ob.x, ob.y};
            float old1[4] = {oc.x, oc.y, od.x, od.y};
            float n0[4], n1[4];
            #pragma unroll
            for (int p = 0; p < 4; ++p) {
                float x, y; unpk(d[p], x, y);
                n0[p] = 0.5f * (old0[p] + lrelu(x));
                n1[p] = 0.5f * (old1[p] + lrelu(y));
            }
            *(float2*)(zb0)     = make_float2(n0[0], n0[1]);
            *(float2*)(zb0 + 2) = make_float2(n0[2], n0[3]);
            *(float2*)(zb1)     = make_float2(n1[0], n1[1]);
            *(float2*)(zb1 + 2) = make_float2(n1[2], n1[3]);
        }
        __syncthreads();
    }

    // ---- class head: logits[o] = bh[o] + <z, wh[o]> ----
    float part[10];
    #pragma unroll
    for (int o = 0; o < 10; ++o) part[o] = 0.f;
    #pragma unroll 1
    for (int i = t; i < 5120; i += 768) {
        int c = i >> 10, rr = (i >> 5) & 31, cc = i & 31;
        float zv = zp[c * 1296 + (rr + 2) * 36 + (cc + 2)];
        #pragma unroll
        for (int o = 0; o < 10; ++o)
            part[o] = fmaf(zv, wh[o * 5120 + i], part[o]);
    }
    float* red = h1;  // reuse as reduction scratch (768*10 = 7680 <= 7776)
    #pragma unroll
    for (int o = 0; o < 10; ++o) red[t * 10 + o] = part[o];
    __syncthreads();
    if (t < 10) {
        float s = bh[t];
        for (int k = 0; k < 768; ++k) s += red[k * 10 + t];
        out[n * 10 + t] = s;
    }
}

extern "C" void kernel_launch(void* const* d_in, const int* in_sizes, int n_in,
                              void* d_out, int out_size) {
    const float* image = (const float*)d_in[0];
    const float* w1    = (const float*)d_in[1];
    const float* b1    = (const float*)d_in[2];
    const float* w2    = (const float*)d_in[3];
    const float* b2    = (const float*)d_in[4];
    const float* wh    = (const float*)d_in[5];
    const float* bh    = (const float*)d_in[6];
    float* out = (float*)d_out;

    const int N = in_sizes[0] / 3072;  // 512 images
    cudaFuncSetAttribute(deq_kernel, cudaFuncAttributeMaxDynamicSharedMemorySize, SMEM_BYTES);
    deq_kernel<<<N, 768, SMEM_BYTES>>>(image, w1, b1, w2, b2, wh, bh, out);
}